// round 5
// baseline (speedup 1.0000x reference)
#include <cuda_runtime.h>
#include <math.h>
#include <stdint.h>

#define NB      128
#define NNODES  1023
#define NLEAVES 512
#define MEM     300
#define INDIM   300

// ---------------- static device scratch (no allocs allowed) ----------------
__device__ float g_C[(size_t)NNODES * NB * MEM];
__device__ float g_H[(size_t)NNODES * NB * MEM];
// gate-blocked transposed weights:
// internal: [10 jtiles][5 gates][32 jl][608 k]  = 1600 x 608
// leaf:     [10 jtiles][3 gates][32 jl][320 k]  =  960 x 320
__device__ float g_WT_int[1600 * 608];
__device__ float g_WT_leaf[960 * 320];

__device__ __forceinline__ float sigmoidf_(float x) { return 1.0f / (1.0f + __expf(-x)); }

__device__ __forceinline__ uint32_t smem_u32(const void* p) {
    uint32_t a;
    asm("{ .reg .u64 t; cvta.to.shared.u64 t, %1; cvt.u32.u64 %0, t; }" : "=r"(a) : "l"(p));
    return a;
}
__device__ __forceinline__ void cp_async16(uint32_t s, const void* g) {
    asm volatile("cp.async.ca.shared.global [%0], [%1], 16;" :: "r"(s), "l"(g) : "memory");
}
__device__ __forceinline__ void cp_commit() { asm volatile("cp.async.commit_group;" ::: "memory"); }
__device__ __forceinline__ void cp_wait1()  { asm volatile("cp.async.wait_group 1;" ::: "memory"); }
__device__ __forceinline__ void cp_wait0()  { asm volatile("cp.async.wait_group 0;" ::: "memory"); }

// round-to-nearest tf32 (removes RZ truncation bias of raw mma operand feed)
__device__ __forceinline__ uint32_t f2tf(float x) {
    uint32_t r;
    asm("cvt.rna.tf32.f32 %0, %1;" : "=r"(r) : "f"(x));
    return r;
}
__device__ __forceinline__ float tf_round(float x) { return __uint_as_float(f2tf(x)); }

// tf32 m16n8k8: D(f32) += A(tf32) * B(tf32)
__device__ __forceinline__ void mma_tf32(float* c, const uint32_t* a, uint32_t b0, uint32_t b1) {
    asm volatile(
        "mma.sync.aligned.m16n8k8.row.col.f32.tf32.tf32.f32 "
        "{%0,%1,%2,%3}, {%4,%5,%6,%7}, {%8,%9}, {%0,%1,%2,%3};"
        : "+f"(c[0]), "+f"(c[1]), "+f"(c[2]), "+f"(c[3])
        : "r"(a[0]), "r"(a[1]), "r"(a[2]), "r"(a[3]), "r"(b0), "r"(b1));
}

// ---------------- weight rearrangement (pre-rounded to tf32-nearest) ----------------
__global__ void build_wt_int(const float* __restrict__ Wiouh, const float* __restrict__ Wfh) {
    int idx = blockIdx.x * blockDim.x + threadIdx.x;
    if (idx >= 1600 * 608) return;
    int n = idx / 608, k = idx % 608;
    int tile = n / 160, rem = n % 160;
    int g = rem / 32, jl = rem % 32;
    int j = tile * 32 + jl;
    float v = 0.f;
    if (j < 300 && k < 600)
        v = (g < 3) ? Wiouh[k * 900 + g * 300 + j] : Wfh[k * 600 + (g - 3) * 300 + j];
    g_WT_int[idx] = tf_round(v);
}
__global__ void build_wt_leaf(const float* __restrict__ Wfioux) {
    int idx = blockIdx.x * blockDim.x + threadIdx.x;
    if (idx >= 960 * 320) return;
    int n = idx / 320, k = idx % 320;
    int tile = n / 96, rem = n % 96;
    int g = rem / 32, jl = rem % 32;
    int j = tile * 32 + jl;
    g_WT_leaf[idx] = (j < 300 && k < 300) ? tf_round(Wfioux[k * 1200 + (g + 1) * 300 + j]) : 0.f;
}

// ---------------- internal: 2 nodes per CTA, fused GEMM+gates ----------------
// grid (10, ceil(k/2)), 256 threads = 8 warps: wm = w&3 (64 rows), wn = w>>2.
// A: [256 x 608] rows m: node m>>7, batch m&127, cols [H_left | H_right].
// B: WT j-tile slice [160 x 608].
// SMEM floats: A0 @0 (256x36), A1 @9216, B0 @18432 (160x36), B1 @24192.
#define IA0 0
#define IA1 9216
#define IB0 18432
#define IB1 24192
#define ISMEM_F 29952   // 119808 bytes

__global__ __launch_bounds__(256, 1) void internal_tc(
    const int* __restrict__ left_idx, const int* __restrict__ right_idx,
    const float* __restrict__ bf, int node_base, int count)
{
    extern __shared__ float sm[];
    const uint32_t sb = smem_u32(sm);
    const int tid  = threadIdx.x;
    const int w    = tid >> 5, lane = tid & 31;
    const int wm   = w & 3, wn = w >> 2;
    const int node0 = node_base + 2 * (int)blockIdx.y;
    const int has2  = (2 * (int)blockIdx.y + 1 < count);
    const int node1 = has2 ? node0 + 1 : node0;
    const int li0 = left_idx[node0], ri0 = right_idx[node0];
    const int li1 = left_idx[node1], ri1 = right_idx[node1];
    const int jbase = blockIdx.x * 32;
    const int jcount = (300 - jbase < 32) ? (300 - jbase) : 32;

    const float* HL0 = g_H + (size_t)li0 * (NB * MEM);
    const float* HR0 = g_H + (size_t)ri0 * (NB * MEM);
    const float* HL1 = g_H + (size_t)li1 * (NB * MEM);
    const float* HR1 = g_H + (size_t)ri1 * (NB * MEM);
    const float* WT  = g_WT_int + (size_t)blockIdx.x * 160 * 608;

    float acc[4][10][4];
    #pragma unroll
    for (int mt = 0; mt < 4; mt++)
        #pragma unroll
        for (int t = 0; t < 10; t++)
            #pragma unroll
            for (int e = 0; e < 4; e++) acc[mt][t][e] = 0.f;

    const int NCH = 19;  // K = 608 (600 + 8 zero pad)
    #define STAGE_INT(CH, AOFF, BOFF) do {                                          \
        int kc = (CH) * 32;                                                         \
        _Pragma("unroll")                                                           \
        for (int i = 0; i < 8; i++) {            /* A: 2048 16B groups */           \
            int v = i * 256 + tid;                                                  \
            int m = v >> 3, kq = v & 7;                                             \
            int kg = kc + kq * 4;                                                   \
            int b  = m & 127;                                                       \
            uint32_t dst = sb + ((AOFF) + m * 36 + kq * 4) * 4;                     \
            if (kg < 300) {                                                         \
                const float* hp = (m < 128) ? HL0 : HL1;                            \
                cp_async16(dst, hp + (size_t)b * MEM + kg);                         \
            } else if (kg < 600) {                                                  \
                const float* hp = (m < 128) ? HR0 : HR1;                            \
                cp_async16(dst, hp + (size_t)b * MEM + kg - 300);                   \
            } else {                                                                \
                *(float4*)(sm + (AOFF) + m * 36 + kq * 4) = make_float4(0,0,0,0);   \
            }                                                                       \
        }                                                                           \
        _Pragma("unroll")                                                           \
        for (int i = 0; i < 5; i++) {            /* B: 1280 16B groups */           \
            int v = i * 256 + tid;                                                  \
            int n = v >> 3, kq = v & 7;                                             \
            uint32_t dst = sb + ((BOFF) + n * 36 + kq * 4) * 4;                     \
            cp_async16(dst, WT + (size_t)n * 608 + kc + kq * 4);                    \
        }                                                                           \
        cp_commit();                                                                \
    } while (0)

    STAGE_INT(0, IA0, IB0);
    #pragma unroll 1
    for (int ch = 0; ch < NCH; ch++) {
        if (ch + 1 < NCH) {
            if ((ch + 1) & 1) STAGE_INT(ch + 1, IA1, IB1);
            else              STAGE_INT(ch + 1, IA0, IB0);
            cp_wait1();
        } else {
            cp_wait0();
        }
        __syncthreads();
        const float* Ab = sm + ((ch & 1) ? IA1 : IA0);
        const float* Bb = sm + ((ch & 1) ? IB1 : IB0);
        #pragma unroll
        for (int ks = 0; ks < 4; ks++) {
            const int c0 = ks * 8 + (lane & 3);
            uint32_t a[4][4];
            #pragma unroll
            for (int mt = 0; mt < 4; mt++) {
                int r = wm * 64 + mt * 16 + (lane >> 2);
                a[mt][0] = __float_as_uint(Ab[r * 36 + c0]);
                a[mt][1] = __float_as_uint(Ab[(r + 8) * 36 + c0]);
                a[mt][2] = __float_as_uint(Ab[r * 36 + c0 + 4]);
                a[mt][3] = __float_as_uint(Ab[(r + 8) * 36 + c0 + 4]);
            }
            #pragma unroll
            for (int t = 0; t < 10; t++) {
                int g = t >> 1, jt = t & 1;
                int n = g * 32 + wn * 16 + jt * 8 + (lane >> 2);
                uint32_t b0 = __float_as_uint(Bb[n * 36 + c0]);
                uint32_t b1 = __float_as_uint(Bb[n * 36 + c0 + 4]);
                #pragma unroll
                for (int mt = 0; mt < 4; mt++)
                    mma_tf32(acc[mt][t], a[mt], b0, b1);
            }
        }
        __syncthreads();
    }
    #undef STAGE_INT

    // ---- fused epilogue: gates fully in registers; H stored tf32-rounded ----
    #pragma unroll
    for (int mt = 0; mt < 4; mt++) {
        #pragma unroll
        for (int jt = 0; jt < 2; jt++) {
            #pragma unroll
            for (int e = 0; e < 4; e++) {
                int jl = wn * 16 + jt * 8 + (lane & 3) * 2 + (e & 1);
                if (jl >= jcount) continue;
                int j = jbase + jl;
                int mloc = wm * 64 + mt * 16 + (lane >> 2) + ((e >> 1) * 8);
                int nd = mloc >> 7, b = mloc & 127;
                int node = nd ? node1 : node0;
                int li = nd ? li1 : li0, ri = nd ? ri1 : ri0;
                float gi = sigmoidf_(acc[mt][0 + jt][e] + bf[300 + j]);
                float go = sigmoidf_(acc[mt][2 + jt][e] + bf[600 + j]);
                float gu = tanhf    (acc[mt][4 + jt][e] + bf[900 + j]);
                float fl = sigmoidf_(acc[mt][6 + jt][e] + bf[j]);
                float fr = sigmoidf_(acc[mt][8 + jt][e] + bf[j]);
                float cl = g_C[((size_t)li * NB + b) * MEM + j];
                float cr = g_C[((size_t)ri * NB + b) * MEM + j];
                float c = gi * gu + fl * cl + fr * cr;
                float h = go * tanhf(c);
                g_C[((size_t)node * NB + b) * MEM + j] = c;
                g_H[((size_t)node * NB + b) * MEM + j] = tf_round(h);
            }
        }
    }
}

// ---------------- leaf: 2 leaves per CTA, fused GEMM+gates ----------------
// grid (10, 256). A: [256 x 320], rows m: leaf m>>7, batch m&127. B: 96 x 320.
#define LA0 0
#define LA1 9216
#define LB0 18432
#define LB1 21888
#define LSMEM_F 25344   // 101376 bytes

__global__ __launch_bounds__(256, 1) void leaf_tc(
    const float* __restrict__ inputs, const float* __restrict__ bf)
{
    extern __shared__ float sm[];
    const uint32_t sb = smem_u32(sm);
    const int tid  = threadIdx.x;
    const int w    = tid >> 5, lane = tid & 31;
    const int wm   = w & 3, wn = w >> 2;
    const int leaf0 = 2 * blockIdx.y;
    const int jbase = blockIdx.x * 32;
    const int jcount = (300 - jbase < 32) ? (300 - jbase) : 32;

    const float* X  = inputs;     // row m: + (m&127)*(NNODES*INDIM) + (leaf0 + (m>>7))*INDIM
    const float* WT = g_WT_leaf + (size_t)blockIdx.x * 96 * 320;

    float acc[4][6][4];
    #pragma unroll
    for (int mt = 0; mt < 4; mt++)
        #pragma unroll
        for (int t = 0; t < 6; t++)
            #pragma unroll
            for (int e = 0; e < 4; e++) acc[mt][t][e] = 0.f;

    const int NCH = 10;  // K = 320 (300 + 20 zero pad)
    #define STAGE_LEAF(CH, AOFF, BOFF) do {                                         \
        int kc = (CH) * 32;                                                         \
        _Pragma("unroll")                                                           \
        for (int i = 0; i < 8; i++) {                                               \
            int v = i * 256 + tid;                                                  \
            int m = v >> 3, kq = v & 7;                                             \
            int kg = kc + kq * 4;                                                   \
            uint32_t dst = sb + ((AOFF) + m * 36 + kq * 4) * 4;                     \
            if (kg < 300) {                                                         \
                const float* xp = X + (size_t)(m & 127) * (NNODES * INDIM)          \
                                    + (leaf0 + (m >> 7)) * INDIM + kg;              \
                cp_async16(dst, xp);                                                \
            } else {                                                                \
                *(float4*)(sm + (AOFF) + m * 36 + kq * 4) = make_float4(0,0,0,0);   \
            }                                                                       \
        }                                                                           \
        _Pragma("unroll")                                                           \
        for (int i = 0; i < 3; i++) {            /* B: 768 16B groups */            \
            int v = i * 256 + tid;                                                  \
            int n = v >> 3, kq = v & 7;                                             \
            uint32_t dst = sb + ((BOFF) + n * 36 + kq * 4) * 4;                     \
            cp_async16(dst, WT + (size_t)n * 320 + kc + kq * 4);                    \
        }                                                                           \
        cp_commit();                                                                \
    } while (0)

    STAGE_LEAF(0, LA0, LB0);
    #pragma unroll 1
    for (int ch = 0; ch < NCH; ch++) {
        if (ch + 1 < NCH) {
            if ((ch + 1) & 1) STAGE_LEAF(ch + 1, LA1, LB1);
            else              STAGE_LEAF(ch + 1, LA0, LB0);
            cp_wait1();
        } else {
            cp_wait0();
        }
        __syncthreads();
        const float* Ab = sm + ((ch & 1) ? LA1 : LA0);
        const float* Bb = sm + ((ch & 1) ? LB1 : LB0);
        #pragma unroll
        for (int ks = 0; ks < 4; ks++) {
            const int c0 = ks * 8 + (lane & 3);
            uint32_t a[4][4];
            #pragma unroll
            for (int mt = 0; mt < 4; mt++) {
                int r = wm * 64 + mt * 16 + (lane >> 2);
                // inputs are raw fp32: round to nearest-tf32 in-register
                a[mt][0] = f2tf(Ab[r * 36 + c0]);
                a[mt][1] = f2tf(Ab[(r + 8) * 36 + c0]);
                a[mt][2] = f2tf(Ab[r * 36 + c0 + 4]);
                a[mt][3] = f2tf(Ab[(r + 8) * 36 + c0 + 4]);
            }
            #pragma unroll
            for (int t = 0; t < 6; t++) {
                int g = t >> 1, jt = t & 1;
                int n = g * 32 + wn * 16 + jt * 8 + (lane >> 2);
                uint32_t b0 = __float_as_uint(Bb[n * 36 + c0]);
                uint32_t b1 = __float_as_uint(Bb[n * 36 + c0 + 4]);
                #pragma unroll
                for (int mt = 0; mt < 4; mt++)
                    mma_tf32(acc[mt][t], a[mt], b0, b1);
            }
        }
        __syncthreads();
    }
    #undef STAGE_LEAF

    #pragma unroll
    for (int mt = 0; mt < 4; mt++) {
        #pragma unroll
        for (int jt = 0; jt < 2; jt++) {
            #pragma unroll
            for (int e = 0; e < 4; e++) {
                int jl = wn * 16 + jt * 8 + (lane & 3) * 2 + (e & 1);
                if (jl >= jcount) continue;
                int j = jbase + jl;
                int mloc = wm * 64 + mt * 16 + (lane >> 2) + ((e >> 1) * 8);
                int leaf = leaf0 + (mloc >> 7), b = mloc & 127;
                float gi = sigmoidf_(acc[mt][0 + jt][e] + bf[300 + j]);
                float go = sigmoidf_(acc[mt][2 + jt][e] + bf[600 + j]);
                float gu = tanhf    (acc[mt][4 + jt][e] + bf[900 + j]);
                float c = gi * gu;
                float h = go * tanhf(c);
                g_C[((size_t)leaf * NB + b) * MEM + j] = c;
                g_H[((size_t)leaf * NB + b) * MEM + j] = tf_round(h);
            }
        }
    }
}

// ---------------- emit root (c, h) ----------------
__global__ void copy_out(float* __restrict__ out) {
    int idx = blockIdx.x * blockDim.x + threadIdx.x;
    if (idx >= 2 * NB * MEM) return;
    size_t root = (size_t)(NNODES - 1) * NB * MEM;
    out[idx] = (idx < NB * MEM) ? g_C[root + idx] : g_H[root + idx - NB * MEM];
}

extern "C" void kernel_launch(void* const* d_in, const int* in_sizes, int n_in,
                              void* d_out, int out_size) {
    const float* inputs   = (const float*)d_in[0];
    const float* Wfioux   = (const float*)d_in[1];
    const float* b_fioux  = (const float*)d_in[2];
    const float* Wiouh    = (const float*)d_in[3];
    const float* Wfh      = (const float*)d_in[4];
    const int*   left_idx = (const int*)d_in[5];
    const int*   right_idx= (const int*)d_in[6];
    float* out = (float*)d_out;

    cudaFuncSetAttribute(internal_tc, cudaFuncAttributeMaxDynamicSharedMemorySize, ISMEM_F * 4);
    cudaFuncSetAttribute(leaf_tc,     cudaFuncAttributeMaxDynamicSharedMemorySize, LSMEM_F * 4);
    cudaFuncSetAttribute(internal_tc, cudaFuncAttributePreferredSharedMemoryCarveout, 100);
    cudaFuncSetAttribute(leaf_tc,     cudaFuncAttributePreferredSharedMemoryCarveout, 100);

    build_wt_int<<<(1600 * 608 + 255) / 256, 256>>>(Wiouh, Wfh);
    build_wt_leaf<<<(960 * 320 + 255) / 256, 256>>>(Wfioux);

    leaf_tc<<<dim3(10, NLEAVES / 2), 256, LSMEM_F * 4>>>(inputs, b_fioux);

    int base = NLEAVES;
    for (int k = NLEAVES / 2; k >= 1; k >>= 1) {
        internal_tc<<<dim3(10, (k + 1) >> 1), 256, ISMEM_F * 4>>>(
            left_idx, right_idx, b_fioux, base, k);
        base += k;
    }
    copy_out<<<(2 * NB * MEM + 255) / 256, 256>>>(out);
}

// round 6
// speedup vs baseline: 1.2379x; 1.2379x over previous
#include <cuda_runtime.h>
#include <math.h>
#include <stdint.h>

#define NB      128
#define NNODES  1023
#define NLEAVES 512
#define MEM     300
#define INDIM   300

// ---------------- static device scratch (no allocs allowed) ----------------
__device__ float g_C[(size_t)NNODES * NB * MEM];
__device__ float g_H[(size_t)NNODES * NB * MEM];
// gate-blocked transposed weights:
// internal: [10 jtiles][5 gates][32 jl][608 k]  = 1600 x 608
// leaf:     [10 jtiles][3 gates][32 jl][320 k]  =  960 x 320
__device__ float g_WT_int[1600 * 608];
__device__ float g_WT_leaf[960 * 320];

__device__ __forceinline__ float sigmoidf_(float x) { return 1.0f / (1.0f + __expf(-x)); }

__device__ __forceinline__ uint32_t smem_u32(const void* p) {
    uint32_t a;
    asm("{ .reg .u64 t; cvta.to.shared.u64 t, %1; cvt.u32.u64 %0, t; }" : "=r"(a) : "l"(p));
    return a;
}
__device__ __forceinline__ void cp_async16(uint32_t s, const void* g) {
    asm volatile("cp.async.ca.shared.global [%0], [%1], 16;" :: "r"(s), "l"(g) : "memory");
}
__device__ __forceinline__ void cp_commit() { asm volatile("cp.async.commit_group;" ::: "memory"); }
__device__ __forceinline__ void cp_wait1()  { asm volatile("cp.async.wait_group 1;" ::: "memory"); }
__device__ __forceinline__ void cp_wait0()  { asm volatile("cp.async.wait_group 0;" ::: "memory"); }

// round-to-nearest tf32 (kills RZ truncation bias; halves per-op error)
__device__ __forceinline__ uint32_t f2tf(float x) {
    uint32_t r;
    asm("cvt.rna.tf32.f32 %0, %1;" : "=r"(r) : "f"(x));
    return r;
}
__device__ __forceinline__ float tf_round(float x) { return __uint_as_float(f2tf(x)); }

// tf32 m16n8k8: D(f32) += A(tf32) * B(tf32)
__device__ __forceinline__ void mma_tf32(float* c, const uint32_t* a, uint32_t b0, uint32_t b1) {
    asm volatile(
        "mma.sync.aligned.m16n8k8.row.col.f32.tf32.tf32.f32 "
        "{%0,%1,%2,%3}, {%4,%5,%6,%7}, {%8,%9}, {%0,%1,%2,%3};"
        : "+f"(c[0]), "+f"(c[1]), "+f"(c[2]), "+f"(c[3])
        : "r"(a[0]), "r"(a[1]), "r"(a[2]), "r"(a[3]), "r"(b0), "r"(b1));
}

// ---------------- weight rearrangement (pre-rounded to tf32-nearest) ----------------
__global__ void build_wt_int(const float* __restrict__ Wiouh, const float* __restrict__ Wfh) {
    int idx = blockIdx.x * blockDim.x + threadIdx.x;
    if (idx >= 1600 * 608) return;
    int n = idx / 608, k = idx % 608;
    int tile = n / 160, rem = n % 160;
    int g = rem / 32, jl = rem % 32;
    int j = tile * 32 + jl;
    float v = 0.f;
    if (j < 300 && k < 600)
        v = (g < 3) ? Wiouh[k * 900 + g * 300 + j] : Wfh[k * 600 + (g - 3) * 300 + j];
    g_WT_int[idx] = tf_round(v);
}
__global__ void build_wt_leaf(const float* __restrict__ Wfioux) {
    int idx = blockIdx.x * blockDim.x + threadIdx.x;
    if (idx >= 960 * 320) return;
    int n = idx / 320, k = idx % 320;
    int tile = n / 96, rem = n % 96;
    int g = rem / 32, jl = rem % 32;
    int j = tile * 32 + jl;
    g_WT_leaf[idx] = (j < 300 && k < 300) ? tf_round(Wfioux[k * 1200 + (g + 1) * 300 + j]) : 0.f;
}

// ---------------- internal-level fused GEMM+gates ----------------
// grid (10, k). 256 threads = 8 warps: wm = w&3 (rows wm*32), wn = w>>2 (jl half).
// A: [128 x 608] = [H[li] | H[ri]] row-major.  B: WT slice [160 x 608].
// K-slot relabeling: MMA ks, thread q=lane&3 takes physical k = ks*8+2q (slot q)
// and ks*8+2q+1 (slot q+4) -> every fragment pair is one LDS.64.
#define IA0 0
#define IA1 4608
#define IB0 9216
#define IB1 14976
#define ISMEM_F 20736   // 82944 bytes

__global__ __launch_bounds__(256, 2) void internal_tc(
    const int* __restrict__ left_idx, const int* __restrict__ right_idx,
    const float* __restrict__ bf, int node_base)
{
    extern __shared__ float sm[];
    const uint32_t sb = smem_u32(sm);
    const int tid  = threadIdx.x;
    const int w    = tid >> 5, lane = tid & 31;
    const int wm   = w & 3, wn = w >> 2;
    const int node = node_base + blockIdx.y;
    const int li = left_idx[node], ri = right_idx[node];
    const int jbase = blockIdx.x * 32;
    const int jcount = (300 - jbase < 32) ? (300 - jbase) : 32;

    const float* HL = g_H + (size_t)li * (NB * MEM);
    const float* HR = g_H + (size_t)ri * (NB * MEM);
    const float* WT = g_WT_int + (size_t)blockIdx.x * 160 * 608;

    float acc[2][10][4];
    #pragma unroll
    for (int mt = 0; mt < 2; mt++)
        #pragma unroll
        for (int t = 0; t < 10; t++)
            #pragma unroll
            for (int e = 0; e < 4; e++) acc[mt][t][e] = 0.f;

    const int NCH = 19;  // K = 608 (600 + 8 zero pad)
    #define STAGE_INT(CH, AOFF, BOFF) do {                                         \
        int kc = (CH) * 32;                                                        \
        _Pragma("unroll")                                                          \
        for (int i = 0; i < 4; i++) {            /* A: 1024 16B groups */          \
            int v = i * 256 + tid;                                                 \
            int m = v >> 3, kq = v & 7;                                            \
            int kg = kc + kq * 4;                                                  \
            uint32_t dst = sb + ((AOFF) + m * 36 + kq * 4) * 4;                    \
            if (kg < 300)      cp_async16(dst, HL + (size_t)m * MEM + kg);         \
            else if (kg < 600) cp_async16(dst, HR + (size_t)m * MEM + kg - 300);   \
            else *(float4*)(sm + (AOFF) + m * 36 + kq * 4) = make_float4(0,0,0,0); \
        }                                                                          \
        _Pragma("unroll")                                                          \
        for (int i = 0; i < 5; i++) {            /* B: 1280 16B groups */          \
            int v = i * 256 + tid;                                                 \
            int n = v >> 3, kq = v & 7;                                            \
            uint32_t dst = sb + ((BOFF) + n * 36 + kq * 4) * 4;                    \
            cp_async16(dst, WT + (size_t)n * 608 + kc + kq * 4);                   \
        }                                                                          \
        cp_commit();                                                               \
    } while (0)

    STAGE_INT(0, IA0, IB0);
    #pragma unroll 1
    for (int ch = 0; ch < NCH; ch++) {
        if (ch + 1 < NCH) {
            if ((ch + 1) & 1) STAGE_INT(ch + 1, IA1, IB1);
            else              STAGE_INT(ch + 1, IA0, IB0);
            cp_wait1();
        } else {
            cp_wait0();
        }
        __syncthreads();
        const float* Ab = sm + ((ch & 1) ? IA1 : IA0);
        const float* Bb = sm + ((ch & 1) ? IB1 : IB0);
        #pragma unroll
        for (int ks = 0; ks < 4; ks++) {
            const int p = ks * 8 + 2 * (lane & 3);     // physical k pair base
            uint32_t a[2][4];
            #pragma unroll
            for (int mt = 0; mt < 2; mt++) {
                int r = wm * 32 + mt * 16 + (lane >> 2);
                float2 a0 = *(const float2*)(Ab + r * 36 + p);
                float2 a1 = *(const float2*)(Ab + (r + 8) * 36 + p);
                a[mt][0] = __float_as_uint(a0.x);
                a[mt][1] = __float_as_uint(a1.x);
                a[mt][2] = __float_as_uint(a0.y);
                a[mt][3] = __float_as_uint(a1.y);
            }
            #pragma unroll
            for (int t = 0; t < 10; t++) {
                int g = t >> 1, jt = t & 1;
                int n = g * 32 + wn * 16 + jt * 8 + (lane >> 2);
                float2 bb = *(const float2*)(Bb + n * 36 + p);
                uint32_t b0 = __float_as_uint(bb.x);
                uint32_t b1 = __float_as_uint(bb.y);
                mma_tf32(acc[0][t], a[0], b0, b1);
                mma_tf32(acc[1][t], a[1], b0, b1);
            }
        }
        __syncthreads();
    }
    #undef STAGE_INT

    // ---- fused epilogue: gates fully in registers; H stored tf32-rounded ----
    #pragma unroll
    for (int mt = 0; mt < 2; mt++) {
        #pragma unroll
        for (int jt = 0; jt < 2; jt++) {
            #pragma unroll
            for (int e = 0; e < 4; e++) {
                int jl = wn * 16 + jt * 8 + (lane & 3) * 2 + (e & 1);
                if (jl >= jcount) continue;
                int j = jbase + jl;
                int m = wm * 32 + mt * 16 + (lane >> 2) + ((e >> 1) * 8);
                float gi = sigmoidf_(acc[mt][0 + jt][e] + bf[300 + j]);
                float go = sigmoidf_(acc[mt][2 + jt][e] + bf[600 + j]);
                float gu = tanhf    (acc[mt][4 + jt][e] + bf[900 + j]);
                float fl = sigmoidf_(acc[mt][6 + jt][e] + bf[j]);
                float fr = sigmoidf_(acc[mt][8 + jt][e] + bf[j]);
                float cl = g_C[((size_t)li * NB + m) * MEM + j];
                float cr = g_C[((size_t)ri * NB + m) * MEM + j];
                float c = gi * gu + fl * cl + fr * cr;
                float h = go * tanhf(c);
                g_C[((size_t)node * NB + m) * MEM + j] = c;
                g_H[((size_t)node * NB + m) * MEM + j] = tf_round(h);
            }
        }
    }
}

// ---------------- leaf fused GEMM+gates ----------------
// grid (10, 512). A: inputs rows (batch) for one leaf, K=320. B: 96 x 320. 3 gates.
#define LA0 0
#define LA1 4608
#define LB0 9216
#define LB1 12672
#define LSMEM_F 16128   // 64512 bytes

__global__ __launch_bounds__(256, 2) void leaf_tc(
    const float* __restrict__ inputs, const float* __restrict__ bf)
{
    extern __shared__ float sm[];
    const uint32_t sb = smem_u32(sm);
    const int tid  = threadIdx.x;
    const int w    = tid >> 5, lane = tid & 31;
    const int wm   = w & 3, wn = w >> 2;
    const int leaf = blockIdx.y;
    const int jbase = blockIdx.x * 32;
    const int jcount = (300 - jbase < 32) ? (300 - jbase) : 32;

    const float* X  = inputs + (size_t)leaf * INDIM;          // + m*(NNODES*INDIM)
    const float* WT = g_WT_leaf + (size_t)blockIdx.x * 96 * 320;

    float acc[2][6][4];
    #pragma unroll
    for (int mt = 0; mt < 2; mt++)
        #pragma unroll
        for (int t = 0; t < 6; t++)
            #pragma unroll
            for (int e = 0; e < 4; e++) acc[mt][t][e] = 0.f;

    const int NCH = 10;  // K = 320 (300 + 20 zero pad)
    #define STAGE_LEAF(CH, AOFF, BOFF) do {                                        \
        int kc = (CH) * 32;                                                        \
        _Pragma("unroll")                                                          \
        for (int i = 0; i < 4; i++) {                                              \
            int v = i * 256 + tid;                                                 \
            int m = v >> 3, kq = v & 7;                                            \
            int kg = kc + kq * 4;                                                  \
            uint32_t dst = sb + ((AOFF) + m * 36 + kq * 4) * 4;                    \
            if (kg < 300) cp_async16(dst, X + (size_t)m * (NNODES * INDIM) + kg);  \
            else *(float4*)(sm + (AOFF) + m * 36 + kq * 4) = make_float4(0,0,0,0); \
        }                                                                          \
        _Pragma("unroll")                                                          \
        for (int i = 0; i < 3; i++) {            /* B: 768 16B groups */           \
            int v = i * 256 + tid;                                                 \
            int n = v >> 3, kq = v & 7;                                            \
            uint32_t dst = sb + ((BOFF) + n * 36 + kq * 4) * 4;                    \
            cp_async16(dst, WT + (size_t)n * 320 + kc + kq * 4);                   \
        }                                                                          \
        cp_commit();                                                               \
    } while (0)

    STAGE_LEAF(0, LA0, LB0);
    #pragma unroll 1
    for (int ch = 0; ch < NCH; ch++) {
        if (ch + 1 < NCH) {
            if ((ch + 1) & 1) STAGE_LEAF(ch + 1, LA1, LB1);
            else              STAGE_LEAF(ch + 1, LA0, LB0);
            cp_wait1();
        } else {
            cp_wait0();
        }
        __syncthreads();
        const float* Ab = sm + ((ch & 1) ? LA1 : LA0);
        const float* Bb = sm + ((ch & 1) ? LB1 : LB0);
        #pragma unroll
        for (int ks = 0; ks < 4; ks++) {
            const int p = ks * 8 + 2 * (lane & 3);
            uint32_t a[2][4];
            #pragma unroll
            for (int mt = 0; mt < 2; mt++) {
                int r = wm * 32 + mt * 16 + (lane >> 2);
                float2 a0 = *(const float2*)(Ab + r * 36 + p);
                float2 a1 = *(const float2*)(Ab + (r + 8) * 36 + p);
                // raw fp32 inputs: round to nearest-tf32 in-register
                a[mt][0] = f2tf(a0.x);
                a[mt][1] = f2tf(a1.x);
                a[mt][2] = f2tf(a0.y);
                a[mt][3] = f2tf(a1.y);
            }
            #pragma unroll
            for (int t = 0; t < 6; t++) {
                int g = t >> 1, jt = t & 1;
                int n = g * 32 + wn * 16 + jt * 8 + (lane >> 2);
                float2 bb = *(const float2*)(Bb + n * 36 + p);
                uint32_t b0 = __float_as_uint(bb.x);
                uint32_t b1 = __float_as_uint(bb.y);
                mma_tf32(acc[0][t], a[0], b0, b1);
                mma_tf32(acc[1][t], a[1], b0, b1);
            }
        }
        __syncthreads();
    }
    #undef STAGE_LEAF

    #pragma unroll
    for (int mt = 0; mt < 2; mt++) {
        #pragma unroll
        for (int jt = 0; jt < 2; jt++) {
            #pragma unroll
            for (int e = 0; e < 4; e++) {
                int jl = wn * 16 + jt * 8 + (lane & 3) * 2 + (e & 1);
                if (jl >= jcount) continue;
                int j = jbase + jl;
                int m = wm * 32 + mt * 16 + (lane >> 2) + ((e >> 1) * 8);
                float gi = sigmoidf_(acc[mt][0 + jt][e] + bf[300 + j]);
                float go = sigmoidf_(acc[mt][2 + jt][e] + bf[600 + j]);
                float gu = tanhf    (acc[mt][4 + jt][e] + bf[900 + j]);
                float c = gi * gu;
                float h = go * tanhf(c);
                g_C[((size_t)leaf * NB + m) * MEM + j] = c;
                g_H[((size_t)leaf * NB + m) * MEM + j] = tf_round(h);
            }
        }
    }
}

// ---------------- emit root (c, h) ----------------
__global__ void copy_out(float* __restrict__ out) {
    int idx = blockIdx.x * blockDim.x + threadIdx.x;
    if (idx >= 2 * NB * MEM) return;
    size_t root = (size_t)(NNODES - 1) * NB * MEM;
    out[idx] = (idx < NB * MEM) ? g_C[root + idx] : g_H[root + idx - NB * MEM];
}

extern "C" void kernel_launch(void* const* d_in, const int* in_sizes, int n_in,
                              void* d_out, int out_size) {
    const float* inputs   = (const float*)d_in[0];
    const float* Wfioux   = (const float*)d_in[1];
    const float* b_fioux  = (const float*)d_in[2];
    const float* Wiouh    = (const float*)d_in[3];
    const float* Wfh      = (const float*)d_in[4];
    const int*   left_idx = (const int*)d_in[5];
    const int*   right_idx= (const int*)d_in[6];
    float* out = (float*)d_out;

    cudaFuncSetAttribute(internal_tc, cudaFuncAttributeMaxDynamicSharedMemorySize, ISMEM_F * 4);
    cudaFuncSetAttribute(leaf_tc,     cudaFuncAttributeMaxDynamicSharedMemorySize, LSMEM_F * 4);
    cudaFuncSetAttribute(internal_tc, cudaFuncAttributePreferredSharedMemoryCarveout, 100);
    cudaFuncSetAttribute(leaf_tc,     cudaFuncAttributePreferredSharedMemoryCarveout, 100);

    build_wt_int<<<(1600 * 608 + 255) / 256, 256>>>(Wiouh, Wfh);
    build_wt_leaf<<<(960 * 320 + 255) / 256, 256>>>(Wfioux);

    leaf_tc<<<dim3(10, NLEAVES), 256, LSMEM_F * 4>>>(inputs, b_fioux);

    int base = NLEAVES;
    for (int k = NLEAVES / 2; k >= 1; k >>= 1) {
        internal_tc<<<dim3(10, k), 256, ISMEM_F * 4>>>(left_idx, right_idx, b_fioux, base);
        base += k;
    }
    copy_out<<<(2 * NB * MEM + 255) / 256, 256>>>(out);
}

// round 8
// speedup vs baseline: 1.8396x; 1.4861x over previous
#include <cuda_runtime.h>
#include <cuda_fp16.h>
#include <math.h>
#include <stdint.h>

#define NB      128
#define NNODES  1023
#define NLEAVES 512
#define MEM     300
#define INDIM   300

// ---------------- static device scratch (no allocs; zero-initialized) ----------------
__device__ float  g_C[(size_t)NNODES * NB * MEM];            // cell states fp32
__device__ __half g_Hh[(size_t)NNODES * NB * 304];           // hidden fp16, k-padded to 304
__device__ float  g_Hroot[NB * MEM];                         // root h in fp32 for output
__device__ __half g_Xh[(size_t)NLEAVES * NB * 320];          // leaf inputs fp16 [leaf*128+b][320]
// gate-blocked transposed weights (fp16):
// internal: [10 jtiles][5 gates][32 jl][608 k]; leaf: [10][3][32][320]
__device__ __half g_WT_int[1600 * 608];
__device__ __half g_WT_leaf[960 * 320];

__device__ __forceinline__ float sigmoidf_(float x) { return 1.0f / (1.0f + __expf(-x)); }

__device__ __forceinline__ uint32_t smem_u32(const void* p) {
    uint32_t a;
    asm("{ .reg .u64 t; cvta.to.shared.u64 t, %1; cvt.u32.u64 %0, t; }" : "=r"(a) : "l"(p));
    return a;
}
__device__ __forceinline__ void cp_async16(uint32_t s, const void* g) {
    asm volatile("cp.async.ca.shared.global [%0], [%1], 16;" :: "r"(s), "l"(g) : "memory");
}
__device__ __forceinline__ void cp_commit() { asm volatile("cp.async.commit_group;" ::: "memory"); }
__device__ __forceinline__ void cp_wait1()  { asm volatile("cp.async.wait_group 1;" ::: "memory"); }
__device__ __forceinline__ void cp_wait0()  { asm volatile("cp.async.wait_group 0;" ::: "memory"); }

__device__ __forceinline__ void ldsm4(uint32_t* r, uint32_t addr) {
    asm volatile("ldmatrix.sync.aligned.m8n8.x4.shared.b16 {%0,%1,%2,%3}, [%4];"
        : "=r"(r[0]), "=r"(r[1]), "=r"(r[2]), "=r"(r[3]) : "r"(addr));
}
// fp16 m16n8k16, fp32 accumulate
__device__ __forceinline__ void mma_f16(float* c, const uint32_t* a, uint32_t b0, uint32_t b1) {
    asm volatile(
        "mma.sync.aligned.m16n8k16.row.col.f32.f16.f16.f32 "
        "{%0,%1,%2,%3}, {%4,%5,%6,%7}, {%8,%9}, {%0,%1,%2,%3};"
        : "+f"(c[0]), "+f"(c[1]), "+f"(c[2]), "+f"(c[3])
        : "r"(a[0]), "r"(a[1]), "r"(a[2]), "r"(a[3]), "r"(b0), "r"(b1));
}

// ---------------- pre-pass kernels ----------------
__global__ void build_wt_int(const float* __restrict__ Wiouh, const float* __restrict__ Wfh) {
    int idx = blockIdx.x * blockDim.x + threadIdx.x;
    if (idx >= 1600 * 608) return;
    int n = idx / 608, k = idx % 608;
    int tile = n / 160, rem = n % 160;
    int g = rem / 32, jl = rem % 32;
    int j = tile * 32 + jl;
    // A layout: [H_left k=0..303 | H_right k=0..303]; weight row = half*300 + kc
    int half = (k >= 304);
    int kc = k - half * 304;                 // child-local k
    int row = half * 300 + kc;               // row in Wiouh/Wfh (600 rows)
    float v = 0.f;
    if (j < 300 && kc < 300)
        v = (g < 3) ? Wiouh[row * 900 + g * 300 + j] : Wfh[row * 600 + (g - 3) * 300 + j];
    g_WT_int[idx] = __float2half_rn(v);
}
__global__ void build_wt_leaf(const float* __restrict__ Wfioux) {
    int idx = blockIdx.x * blockDim.x + threadIdx.x;
    if (idx >= 960 * 320) return;
    int n = idx / 320, k = idx % 320;
    int tile = n / 96, rem = n % 96;
    int g = rem / 32, jl = rem % 32;
    int j = tile * 32 + jl;
    float v = (j < 300 && k < 300) ? Wfioux[k * 1200 + (g + 1) * 300 + j] : 0.f;
    g_WT_leaf[idx] = __float2half_rn(v);
}
// inputs[b][leaf][k] fp32 -> g_Xh[(leaf*128+b)][k] fp16 (coalesced rows)
__global__ void convert_x(const float* __restrict__ inputs) {
    int idx = blockIdx.x * blockDim.x + threadIdx.x;
    if (idx >= NLEAVES * NB * 320) return;
    int k = idx % 320;
    int r = idx / 320;
    int b = r & 127, leaf = r >> 7;
    float v = (k < 300) ? inputs[(size_t)b * (NNODES * INDIM) + leaf * INDIM + k] : 0.f;
    g_Xh[idx] = __float2half_rn(v);
}

// ---------------- internal-level fused GEMM+gates (fp16 MMA) ----------------
// grid (10, k). 256 threads = 8 warps: wm = w&3 (rows wm*32), wn = w>>2 (jl half).
// A: [128 x 608] = [Hh[li] | Hh[ri]] (each 304-padded).  B: WT slice [160 x 608].
// SMEM (halfs, row stride 40 = 80B, 16B-aligned, LDSM conflict-free):
#define IA0 0
#define IA1 5120
#define IB0 10240
#define IB1 16640
#define ISMEM_H 23040   // 46080 bytes

__global__ __launch_bounds__(256, 2) void internal_tc(
    const int* __restrict__ left_idx, const int* __restrict__ right_idx,
    const float* __restrict__ bf, int node_base)
{
    extern __shared__ __half smh[];
    const uint32_t sb = smem_u32(smh);
    const int tid  = threadIdx.x;
    const int w    = tid >> 5, lane = tid & 31;
    const int wm   = w & 3, wn = w >> 2;
    const int node = node_base + blockIdx.y;
    const int li = left_idx[node], ri = right_idx[node];
    const int jbase = blockIdx.x * 32;
    const int jcount = (300 - jbase < 32) ? (300 - jbase) : 32;

    const __half* HL = g_Hh + (size_t)li * (NB * 304);
    const __half* HR = g_Hh + (size_t)ri * (NB * 304);
    const __half* WT = g_WT_int + (size_t)blockIdx.x * 160 * 608;

    // per-lane ldmatrix address components (halfs)
    const int a_lane = (lane & 15) * 40 + ((lane >> 4) & 1) * 8;
    const int b_lane = (lane & 7) * 40 + (lane >> 3) * 8;

    float acc[2][10][4];
    #pragma unroll
    for (int mt = 0; mt < 2; mt++)
        #pragma unroll
        for (int t = 0; t < 10; t++)
            #pragma unroll
            for (int e = 0; e < 4; e++) acc[mt][t][e] = 0.f;

    const int NCH = 19;  // K = 608
    #define STAGE_INT(CH, AOFF, BOFF) do {                                         \
        int kc = (CH) * 32;                                                        \
        _Pragma("unroll")                                                          \
        for (int i = 0; i < 2; i++) {            /* A: 512 16B groups */           \
            int v = i * 256 + tid;                                                 \
            int m = v >> 2, kq = v & 3;                                            \
            int k = kc + kq * 8;                                                   \
            uint32_t dst = sb + ((AOFF) + m * 40 + kq * 8) * 2;                    \
            if (k < 304) cp_async16(dst, HL + (size_t)m * 304 + k);                \
            else         cp_async16(dst, HR + (size_t)m * 304 + (k - 304));        \
        }                                                                          \
        _Pragma("unroll")                                                          \
        for (int i = 0; i < 3; i++) {            /* B: 640 16B groups */           \
            int v = i * 256 + tid;                                                 \
            if (v < 640) {                                                         \
                int n = v >> 2, kq = v & 3;                                        \
                uint32_t dst = sb + ((BOFF) + n * 40 + kq * 8) * 2;                \
                cp_async16(dst, WT + (size_t)n * 608 + kc + kq * 8);               \
            }                                                                      \
        }                                                                          \
        cp_commit();                                                               \
    } while (0)

    STAGE_INT(0, IA0, IB0);
    #pragma unroll 1
    for (int ch = 0; ch < NCH; ch++) {
        if (ch + 1 < NCH) {
            if ((ch + 1) & 1) STAGE_INT(ch + 1, IA1, IB1);
            else              STAGE_INT(ch + 1, IA0, IB0);
            cp_wait1();
        } else {
            cp_wait0();
        }
        __syncthreads();
        const int Ab = (ch & 1) ? IA1 : IA0;
        const int Bb = (ch & 1) ? IB1 : IB0;
        uint32_t a[2][2][4];    // [mt][kstep][4]
        #pragma unroll
        for (int mt = 0; mt < 2; mt++)
            #pragma unroll
            for (int cp = 0; cp < 2; cp++)
                ldsm4(a[mt][cp],
                      sb + (Ab + (wm * 32 + mt * 16) * 40 + cp * 16 + a_lane) * 2);
        #pragma unroll
        for (int t = 0; t < 10; t++) {
            int g = t >> 1, jt = t & 1;
            int n0 = g * 32 + wn * 16 + jt * 8;
            uint32_t b[4];      // kstep0: b[0],b[1]; kstep1: b[2],b[3]
            ldsm4(b, sb + (Bb + n0 * 40 + b_lane) * 2);
            #pragma unroll
            for (int s = 0; s < 2; s++) {
                mma_f16(acc[0][t], a[0][s], b[s * 2], b[s * 2 + 1]);
                mma_f16(acc[1][t], a[1][s], b[s * 2], b[s * 2 + 1]);
            }
        }
        __syncthreads();
    }
    #undef STAGE_INT

    // ---- fused epilogue ----
    const bool isroot = (node == NNODES - 1);
    #pragma unroll
    for (int mt = 0; mt < 2; mt++) {
        #pragma unroll
        for (int jt = 0; jt < 2; jt++) {
            #pragma unroll
            for (int e = 0; e < 4; e++) {
                int jl = wn * 16 + jt * 8 + (lane & 3) * 2 + (e & 1);
                if (jl >= jcount) continue;
                int j = jbase + jl;
                int m = wm * 32 + mt * 16 + (lane >> 2) + ((e >> 1) * 8);
                float gi = sigmoidf_(acc[mt][0 + jt][e] + bf[300 + j]);
                float go = sigmoidf_(acc[mt][2 + jt][e] + bf[600 + j]);
                float gu = tanhf    (acc[mt][4 + jt][e] + bf[900 + j]);
                float fl = sigmoidf_(acc[mt][6 + jt][e] + bf[j]);
                float fr = sigmoidf_(acc[mt][8 + jt][e] + bf[j]);
                float cl = g_C[((size_t)li * NB + m) * MEM + j];
                float cr = g_C[((size_t)ri * NB + m) * MEM + j];
                float c = gi * gu + fl * cl + fr * cr;
                float h = go * tanhf(c);
                g_C[((size_t)node * NB + m) * MEM + j] = c;
                g_Hh[((size_t)node * NB + m) * 304 + j] = __float2half_rn(h);
                if (isroot) g_Hroot[m * MEM + j] = h;
            }
        }
    }
}

// ---------------- leaf fused GEMM+gates (fp16 MMA) ----------------
// grid (10, 512). A: g_Xh rows [leaf*128+b][320]. B: WT_leaf slice [96 x 320].
#define LA0 0
#define LA1 5120
#define LB0 10240
#define LB1 14080
#define LSMEM_H 17920   // 35840 bytes

__global__ __launch_bounds__(256, 2) void leaf_tc(const float* __restrict__ bf)
{
    extern __shared__ __half smh[];
    const uint32_t sb = smem_u32(smh);
    const int tid  = threadIdx.x;
    const int w    = tid >> 5, lane = tid & 31;
    const int wm   = w & 3, wn = w >> 2;
    const int leaf = blockIdx.y;
    const int jbase = blockIdx.x * 32;
    const int jcount = (300 - jbase < 32) ? (300 - jbase) : 32;

    const __half* X  = g_Xh + (size_t)leaf * (NB * 320);
    const __half* WT = g_WT_leaf + (size_t)blockIdx.x * 96 * 320;

    const int a_lane = (lane & 15) * 40 + ((lane >> 4) & 1) * 8;
    const int b_lane = (lane & 7) * 40 + (lane >> 3) * 8;

    float acc[2][6][4];
    #pragma unroll
    for (int mt = 0; mt < 2; mt++)
        #pragma unroll
        for (int t = 0; t < 6; t++)
            #pragma unroll
            for (int e = 0; e < 4; e++) acc[mt][t][e] = 0.f;

    const int NCH = 10;  // K = 320
    #define STAGE_LEAF(CH, AOFF, BOFF) do {                                        \
        int kc = (CH) * 32;                                                        \
        _Pragma("unroll")                                                          \
        for (int i = 0; i < 2; i++) {            /* A: 512 groups */               \
            int v = i * 256 + tid;                                                 \
            int m = v >> 2, kq = v & 3;                                            \
            uint32_t dst = sb + ((AOFF) + m * 40 + kq * 8) * 2;                    \
            cp_async16(dst, X + (size_t)m * 320 + kc + kq * 8);                    \
        }                                                                          \
        _Pragma("unroll")                                                          \
        for (int i = 0; i < 2; i++) {            /* B: 384 groups */               \
            int v = i * 256 + tid;                                                 \
            if (v < 384) {                                                         \
                int n = v >> 2, kq = v & 3;                                        \
                uint32_t dst = sb + ((BOFF) + n * 40 + kq * 8) * 2;                \
                cp_async16(dst, WT + (size_t)n * 320 + kc + kq * 8);               \
            }                                                                      \
        }                                                                          \
        cp_commit();                                                               \
    } while (0)

    STAGE_LEAF(0, LA0, LB0);
    #pragma unroll 1
    for (int ch = 0; ch < NCH; ch++) {
        if (ch + 1 < NCH) {
            if ((ch + 1) & 1) STAGE_LEAF(ch + 1, LA1, LB1);
            else              STAGE_LEAF(ch + 1, LA0, LB0);
            cp_wait1();
        } else {
            cp_wait0();
        }
        __syncthreads();
        const int Ab = (ch & 1) ? LA1 : LA0;
        const int Bb = (ch & 1) ? LB1 : LB0;
        uint32_t a[2][2][4];
        #pragma unroll
        for (int mt = 0; mt < 2; mt++)
            #pragma unroll
            for (int cp = 0; cp < 2; cp++)
                ldsm4(a[mt][cp],
                      sb + (Ab + (wm * 32 + mt * 16) * 40 + cp * 16 + a_lane) * 2);
        #pragma unroll
        for (int t = 0; t < 6; t++) {
            int g = t >> 1, jt = t & 1;
            int n0 = g * 32 + wn * 16 + jt * 8;
            uint32_t b[4];
            ldsm4(b, sb + (Bb + n0 * 40 + b_lane) * 2);
            #pragma unroll
            for (int s = 0; s < 2; s++) {
                mma_f16(acc[0][t], a[0][s], b[s * 2], b[s * 2 + 1]);
                mma_f16(acc[1][t], a[1][s], b[s * 2], b[s * 2 + 1]);
            }
        }
        __syncthreads();
    }
    #undef STAGE_LEAF

    #pragma unroll
    for (int mt = 0; mt < 2; mt++) {
        #pragma unroll
        for (int jt = 0; jt < 2; jt++) {
            #pragma unroll
            for (int e = 0; e < 4; e++) {
                int jl = wn * 16 + jt * 8 + (lane & 3) * 2 + (e & 1);
                if (jl >= jcount) continue;
                int j = jbase + jl;
                int m = wm * 32 + mt * 16 + (lane >> 2) + ((e >> 1) * 8);
                float gi = sigmoidf_(acc[mt][0 + jt][e] + bf[300 + j]);
                float go = sigmoidf_(acc[mt][2 + jt][e] + bf[600 + j]);
                float gu = tanhf    (acc[mt][4 + jt][e] + bf[900 + j]);
                float c = gi * gu;
                float h = go * tanhf(c);
                g_C[((size_t)leaf * NB + m) * MEM + j] = c;
                g_Hh[((size_t)leaf * NB + m) * 304 + j] = __float2half_rn(h);
            }
        }
    }
}

// ---------------- emit root (c, h) ----------------
__global__ void copy_out(float* __restrict__ out) {
    int idx = blockIdx.x * blockDim.x + threadIdx.x;
    if (idx >= 2 * NB * MEM) return;
    size_t root = (size_t)(NNODES - 1) * NB * MEM;
    out[idx] = (idx < NB * MEM) ? g_C[root + idx] : g_Hroot[idx - NB * MEM];
}

extern "C" void kernel_launch(void* const* d_in, const int* in_sizes, int n_in,
                              void* d_out, int out_size) {
    const float* inputs   = (const float*)d_in[0];
    const float* Wfioux   = (const float*)d_in[1];
    const float* b_fioux  = (const float*)d_in[2];
    const float* Wiouh    = (const float*)d_in[3];
    const float* Wfh      = (const float*)d_in[4];
    const int*   left_idx = (const int*)d_in[5];
    const int*   right_idx= (const int*)d_in[6];
    float* out = (float*)d_out;

    cudaFuncSetAttribute(internal_tc, cudaFuncAttributeMaxDynamicSharedMemorySize, ISMEM_H * 2);
    cudaFuncSetAttribute(leaf_tc,     cudaFuncAttributeMaxDynamicSharedMemorySize, LSMEM_H * 2);
    cudaFuncSetAttribute(internal_tc, cudaFuncAttributePreferredSharedMemoryCarveout, 100);
    cudaFuncSetAttribute(leaf_tc,     cudaFuncAttributePreferredSharedMemoryCarveout, 100);

    build_wt_int<<<(1600 * 608 + 255) / 256, 256>>>(Wiouh, Wfh);
    build_wt_leaf<<<(960 * 320 + 255) / 256, 256>>>(Wfioux);
    convert_x<<<(NLEAVES * NB * 320 + 255) / 256, 256>>>(inputs);

    leaf_tc<<<dim3(10, NLEAVES), 256, LSMEM_H * 2>>>(b_fioux);

    int base = NLEAVES;
    for (int k = NLEAVES / 2; k >= 1; k >>= 1) {
        internal_tc<<<dim3(10, k), 256, ISMEM_H * 2>>>(left_idx, right_idx, b_fioux, base);
        base += k;
    }
    copy_out<<<(2 * NB * MEM + 255) / 256, 256>>>(out);
}

// round 9
// speedup vs baseline: 2.0791x; 1.1302x over previous
#include <cuda_runtime.h>
#include <cuda_fp16.h>
#include <math.h>
#include <stdint.h>

#define NB      128
#define NNODES  1023
#define NLEAVES 512
#define MEM     300
#define INDIM   300

// ---------------- static device scratch (no allocs; zero-initialized) ----------------
__device__ float  g_C[(size_t)NNODES * NB * MEM];            // cell states fp32
__device__ __half g_Hh[(size_t)NNODES * NB * 320];           // hidden fp16, k-padded to 320
__device__ float  g_Hroot[NB * MEM];                         // root h in fp32 for output
__device__ __half g_Xh[(size_t)NLEAVES * NB * 320];          // leaf inputs fp16 [leaf*128+b][320]
// gate-blocked transposed weights (fp16):
// internal: [10 jtiles][5 gates][32 jl][640 k]; leaf: [10][3][32][320]
__device__ __half g_WT_int[1600 * 640];
__device__ __half g_WT_leaf[960 * 320];

__device__ __forceinline__ float sigmoidf_(float x) { return 1.0f / (1.0f + __expf(-x)); }

__device__ __forceinline__ uint32_t smem_u32(const void* p) {
    uint32_t a;
    asm("{ .reg .u64 t; cvta.to.shared.u64 t, %1; cvt.u32.u64 %0, t; }" : "=r"(a) : "l"(p));
    return a;
}
__device__ __forceinline__ void cp_async16(uint32_t s, const void* g) {
    asm volatile("cp.async.ca.shared.global [%0], [%1], 16;" :: "r"(s), "l"(g) : "memory");
}
__device__ __forceinline__ void cp_commit() { asm volatile("cp.async.commit_group;" ::: "memory"); }
__device__ __forceinline__ void cp_wait1()  { asm volatile("cp.async.wait_group 1;" ::: "memory"); }
__device__ __forceinline__ void cp_wait0()  { asm volatile("cp.async.wait_group 0;" ::: "memory"); }

__device__ __forceinline__ void ldsm4(uint32_t* r, uint32_t addr) {
    asm volatile("ldmatrix.sync.aligned.m8n8.x4.shared.b16 {%0,%1,%2,%3}, [%4];"
        : "=r"(r[0]), "=r"(r[1]), "=r"(r[2]), "=r"(r[3]) : "r"(addr));
}
// fp16 m16n8k16, fp32 accumulate
__device__ __forceinline__ void mma_f16(float* c, const uint32_t* a, uint32_t b0, uint32_t b1) {
    asm volatile(
        "mma.sync.aligned.m16n8k16.row.col.f32.f16.f16.f32 "
        "{%0,%1,%2,%3}, {%4,%5,%6,%7}, {%8,%9}, {%0,%1,%2,%3};"
        : "+f"(c[0]), "+f"(c[1]), "+f"(c[2]), "+f"(c[3])
        : "r"(a[0]), "r"(a[1]), "r"(a[2]), "r"(a[3]), "r"(b0), "r"(b1));
}

// ---------------- pre-pass kernels ----------------
__global__ void build_wt_int(const float* __restrict__ Wiouh, const float* __restrict__ Wfh) {
    int idx = blockIdx.x * blockDim.x + threadIdx.x;
    if (idx >= 1600 * 640) return;
    int n = idx / 640, k = idx % 640;
    int tile = n / 160, rem = n % 160;
    int g = rem / 32, jl = rem % 32;
    int j = tile * 32 + jl;
    // A layout: [H_left k=0..319 | H_right k=0..319]; weight row = half*300 + kc
    int half = (k >= 320);
    int kc = k - half * 320;
    int row = half * 300 + kc;
    float v = 0.f;
    if (j < 300 && kc < 300)
        v = (g < 3) ? Wiouh[row * 900 + g * 300 + j] : Wfh[row * 600 + (g - 3) * 300 + j];
    g_WT_int[idx] = __float2half_rn(v);
}
__global__ void build_wt_leaf(const float* __restrict__ Wfioux) {
    int idx = blockIdx.x * blockDim.x + threadIdx.x;
    if (idx >= 960 * 320) return;
    int n = idx / 320, k = idx % 320;
    int tile = n / 96, rem = n % 96;
    int g = rem / 32, jl = rem % 32;
    int j = tile * 32 + jl;
    float v = (j < 300 && k < 300) ? Wfioux[k * 1200 + (g + 1) * 300 + j] : 0.f;
    g_WT_leaf[idx] = __float2half_rn(v);
}
// inputs[b][leaf][k] fp32 -> g_Xh[(leaf*128+b)][k] fp16 (coalesced rows)
__global__ void convert_x(const float* __restrict__ inputs) {
    int idx = blockIdx.x * blockDim.x + threadIdx.x;
    if (idx >= NLEAVES * NB * 320) return;
    int k = idx % 320;
    int r = idx / 320;
    int b = r & 127, leaf = r >> 7;
    float v = (k < 300) ? inputs[(size_t)b * (NNODES * INDIM) + leaf * INDIM + k] : 0.f;
    g_Xh[idx] = __float2half_rn(v);
}

// ---------------- internal-level fused GEMM+gates (fp16 MMA, K-chunk 64) ----------------
// grid (10, k). 256 threads = 8 warps: wm = w&3 (rows wm*32), wn = w>>2 (jl half).
// A: [128 x 640] = [Hh[li] | Hh[ri]] (each 320-padded).  B: WT slice [160 x 640].
// SMEM halfs, row stride 72 (144 B == 16 mod 128 -> LDSM conflict-free, 16B aligned).
#define IA0 0
#define IA1 9216
#define IB0 18432
#define IB1 29952
#define ISMEM_H 41472   // 82944 bytes

__global__ __launch_bounds__(256, 2) void internal_tc(
    const int* __restrict__ left_idx, const int* __restrict__ right_idx,
    const float* __restrict__ bf, int node_base)
{
    extern __shared__ __half smh[];
    const uint32_t sb = smem_u32(smh);
    const int tid  = threadIdx.x;
    const int w    = tid >> 5, lane = tid & 31;
    const int wm   = w & 3, wn = w >> 2;
    const int node = node_base + blockIdx.y;
    const int li = left_idx[node], ri = right_idx[node];
    const int jbase = blockIdx.x * 32;
    const int jcount = (300 - jbase < 32) ? (300 - jbase) : 32;

    const __half* HL = g_Hh + (size_t)li * (NB * 320);
    const __half* HR = g_Hh + (size_t)ri * (NB * 320);
    const __half* WT = g_WT_int + (size_t)blockIdx.x * 160 * 640;

    const int a_lane = (lane & 15) * 72 + ((lane >> 4) & 1) * 8;
    const int b_lane = (lane & 7) * 72 + (lane >> 3) * 8;

    float acc[2][10][4];
    #pragma unroll
    for (int mt = 0; mt < 2; mt++)
        #pragma unroll
        for (int t = 0; t < 10; t++)
            #pragma unroll
            for (int e = 0; e < 4; e++) acc[mt][t][e] = 0.f;

    const int NCH = 10;  // K = 640, chunk 64
    #define STAGE_INT(CH, AOFF, BOFF) do {                                         \
        int kc = (CH) * 64;                                                        \
        _Pragma("unroll")                                                          \
        for (int i = 0; i < 4; i++) {            /* A: 1024 16B groups */          \
            int v = i * 256 + tid;                                                 \
            int m = v >> 3, kq = v & 7;                                            \
            int k = kc + kq * 8;                                                   \
            uint32_t dst = sb + ((AOFF) + m * 72 + kq * 8) * 2;                    \
            if (k < 320) cp_async16(dst, HL + (size_t)m * 320 + k);                \
            else         cp_async16(dst, HR + (size_t)m * 320 + (k - 320));        \
        }                                                                          \
        _Pragma("unroll")                                                          \
        for (int i = 0; i < 5; i++) {            /* B: 1280 16B groups */          \
            int v = i * 256 + tid;                                                 \
            int n = v >> 3, kq = v & 7;                                            \
            uint32_t dst = sb + ((BOFF) + n * 72 + kq * 8) * 2;                    \
            cp_async16(dst, WT + (size_t)n * 640 + kc + kq * 8);                   \
        }                                                                          \
        cp_commit();                                                               \
    } while (0)

    STAGE_INT(0, IA0, IB0);
    #pragma unroll 1
    for (int ch = 0; ch < NCH; ch++) {
        if (ch + 1 < NCH) {
            if ((ch + 1) & 1) STAGE_INT(ch + 1, IA1, IB1);
            else              STAGE_INT(ch + 1, IA0, IB0);
            cp_wait1();
        } else {
            cp_wait0();
        }
        __syncthreads();
        const int Ab = (ch & 1) ? IA1 : IA0;
        const int Bb = (ch & 1) ? IB1 : IB0;
        #pragma unroll
        for (int kh = 0; kh < 2; kh++) {         // two 32-wide k halves
            uint32_t a[2][2][4];                 // [mt][kstep-in-half][4]
            #pragma unroll
            for (int mt = 0; mt < 2; mt++)
                #pragma unroll
                for (int s = 0; s < 2; s++)
                    ldsm4(a[mt][s],
                          sb + (Ab + (wm * 32 + mt * 16) * 72 + (kh * 2 + s) * 16 + a_lane) * 2);
            #pragma unroll
            for (int t = 0; t < 10; t++) {
                int g = t >> 1, jt = t & 1;
                int n0 = g * 32 + wn * 16 + jt * 8;
                uint32_t b[4];
                ldsm4(b, sb + (Bb + n0 * 72 + kh * 32 + b_lane) * 2);
                #pragma unroll
                for (int s = 0; s < 2; s++) {
                    mma_f16(acc[0][t], a[0][s], b[s * 2], b[s * 2 + 1]);
                    mma_f16(acc[1][t], a[1][s], b[s * 2], b[s * 2 + 1]);
                }
            }
        }
        __syncthreads();
    }
    #undef STAGE_INT

    // ---- fused epilogue ----
    const bool isroot = (node == NNODES - 1);
    #pragma unroll
    for (int mt = 0; mt < 2; mt++) {
        #pragma unroll
        for (int jt = 0; jt < 2; jt++) {
            #pragma unroll
            for (int e = 0; e < 4; e++) {
                int jl = wn * 16 + jt * 8 + (lane & 3) * 2 + (e & 1);
                if (jl >= jcount) continue;
                int j = jbase + jl;
                int m = wm * 32 + mt * 16 + (lane >> 2) + ((e >> 1) * 8);
                float gi = sigmoidf_(acc[mt][0 + jt][e] + bf[300 + j]);
                float go = sigmoidf_(acc[mt][2 + jt][e] + bf[600 + j]);
                float gu = tanhf    (acc[mt][4 + jt][e] + bf[900 + j]);
                float fl = sigmoidf_(acc[mt][6 + jt][e] + bf[j]);
                float fr = sigmoidf_(acc[mt][8 + jt][e] + bf[j]);
                float cl = g_C[((size_t)li * NB + m) * MEM + j];
                float cr = g_C[((size_t)ri * NB + m) * MEM + j];
                float c = gi * gu + fl * cl + fr * cr;
                float h = go * tanhf(c);
                g_C[((size_t)node * NB + m) * MEM + j] = c;
                g_Hh[((size_t)node * NB + m) * 320 + j] = __float2half_rn(h);
                if (isroot) g_Hroot[m * MEM + j] = h;
            }
        }
    }
}

// ---------------- leaf fused GEMM+gates (fp16 MMA, K-chunk 64) ----------------
// grid (10, 512). A: g_Xh rows [leaf*128+b][320]. B: WT_leaf slice [96 x 320].
#define LA0 0
#define LA1 9216
#define LB0 18432
#define LB1 25344
#define LSMEM_H 32256   // 64512 bytes

__global__ __launch_bounds__(256, 2) void leaf_tc(const float* __restrict__ bf)
{
    extern __shared__ __half smh[];
    const uint32_t sb = smem_u32(smh);
    const int tid  = threadIdx.x;
    const int w    = tid >> 5, lane = tid & 31;
    const int wm   = w & 3, wn = w >> 2;
    const int leaf = blockIdx.y;
    const int jbase = blockIdx.x * 32;
    const int jcount = (300 - jbase < 32) ? (300 - jbase) : 32;

    const __half* X  = g_Xh + (size_t)leaf * (NB * 320);
    const __half* WT = g_WT_leaf + (size_t)blockIdx.x * 96 * 320;

    const int a_lane = (lane & 15) * 72 + ((lane >> 4) & 1) * 8;
    const int b_lane = (lane & 7) * 72 + (lane >> 3) * 8;

    float acc[2][6][4];
    #pragma unroll
    for (int mt = 0; mt < 2; mt++)
        #pragma unroll
        for (int t = 0; t < 6; t++)
            #pragma unroll
            for (int e = 0; e < 4; e++) acc[mt][t][e] = 0.f;

    const int NCH = 5;   // K = 320, chunk 64
    #define STAGE_LEAF(CH, AOFF, BOFF) do {                                        \
        int kc = (CH) * 64;                                                        \
        _Pragma("unroll")                                                          \
        for (int i = 0; i < 4; i++) {            /* A: 1024 groups */              \
            int v = i * 256 + tid;                                                 \
            int m = v >> 3, kq = v & 7;                                            \
            uint32_t dst = sb + ((AOFF) + m * 72 + kq * 8) * 2;                    \
            cp_async16(dst, X + (size_t)m * 320 + kc + kq * 8);                    \
        }                                                                          \
        _Pragma("unroll")                                                          \
        for (int i = 0; i < 3; i++) {            /* B: 768 groups */               \
            int v = i * 256 + tid;                                                 \
            if (v < 768) {                                                         \
                int n = v >> 3, kq = v & 7;                                        \
                uint32_t dst = sb + ((BOFF) + n * 72 + kq * 8) * 2;                \
                cp_async16(dst, WT + (size_t)n * 320 + kc + kq * 8);               \
            }                                                                      \
        }                                                                          \
        cp_commit();                                                               \
    } while (0)

    STAGE_LEAF(0, LA0, LB0);
    #pragma unroll 1
    for (int ch = 0; ch < NCH; ch++) {
        if (ch + 1 < NCH) {
            if ((ch + 1) & 1) STAGE_LEAF(ch + 1, LA1, LB1);
            else              STAGE_LEAF(ch + 1, LA0, LB0);
            cp_wait1();
        } else {
            cp_wait0();
        }
        __syncthreads();
        const int Ab = (ch & 1) ? LA1 : LA0;
        const int Bb = (ch & 1) ? LB1 : LB0;
        #pragma unroll
        for (int kh = 0; kh < 2; kh++) {
            uint32_t a[2][2][4];
            #pragma unroll
            for (int mt = 0; mt < 2; mt++)
                #pragma unroll
                for (int s = 0; s < 2; s++)
                    ldsm4(a[mt][s],
                          sb + (Ab + (wm * 32 + mt * 16) * 72 + (kh * 2 + s) * 16 + a_lane) * 2);
            #pragma unroll
            for (int t = 0; t < 6; t++) {
                int g = t >> 1, jt = t & 1;
                int n0 = g * 32 + wn * 16 + jt * 8;
                uint32_t b[4];
                ldsm4(b, sb + (Bb + n0 * 72 + kh * 32 + b_lane) * 2);
                #pragma unroll
                for (int s = 0; s < 2; s++) {
                    mma_f16(acc[0][t], a[0][s], b[s * 2], b[s * 2 + 1]);
                    mma_f16(acc[1][t], a[1][s], b[s * 2], b[s * 2 + 1]);
                }
            }
        }
        __syncthreads();
    }
    #undef STAGE_LEAF

    #pragma unroll
    for (int mt = 0; mt < 2; mt++) {
        #pragma unroll
        for (int jt = 0; jt < 2; jt++) {
            #pragma unroll
            for (int e = 0; e < 4; e++) {
                int jl = wn * 16 + jt * 8 + (lane & 3) * 2 + (e & 1);
                if (jl >= jcount) continue;
                int j = jbase + jl;
                int m = wm * 32 + mt * 16 + (lane >> 2) + ((e >> 1) * 8);
                float gi = sigmoidf_(acc[mt][0 + jt][e] + bf[300 + j]);
                float go = sigmoidf_(acc[mt][2 + jt][e] + bf[600 + j]);
                float gu = tanhf    (acc[mt][4 + jt][e] + bf[900 + j]);
                float c = gi * gu;
                float h = go * tanhf(c);
                g_C[((size_t)leaf * NB + m) * MEM + j] = c;
                g_Hh[((size_t)leaf * NB + m) * 320 + j] = __float2half_rn(h);
            }
        }
    }
}

// ---------------- emit root (c, h) ----------------
__global__ void copy_out(float* __restrict__ out) {
    int idx = blockIdx.x * blockDim.x + threadIdx.x;
    if (idx >= 2 * NB * MEM) return;
    size_t root = (size_t)(NNODES - 1) * NB * MEM;
    out[idx] = (idx < NB * MEM) ? g_C[root + idx] : g_Hroot[idx - NB * MEM];
}

extern "C" void kernel_launch(void* const* d_in, const int* in_sizes, int n_in,
                              void* d_out, int out_size) {
    const float* inputs   = (const float*)d_in[0];
    const float* Wfioux   = (const float*)d_in[1];
    const float* b_fioux  = (const float*)d_in[2];
    const float* Wiouh    = (const float*)d_in[3];
    const float* Wfh      = (const float*)d_in[4];
    const int*   left_idx = (const int*)d_in[5];
    const int*   right_idx= (const int*)d_in[6];
    float* out = (float*)d_out;

    cudaFuncSetAttribute(internal_tc, cudaFuncAttributeMaxDynamicSharedMemorySize, ISMEM_H * 2);
    cudaFuncSetAttribute(leaf_tc,     cudaFuncAttributeMaxDynamicSharedMemorySize, LSMEM_H * 2);
    cudaFuncSetAttribute(internal_tc, cudaFuncAttributePreferredSharedMemoryCarveout, 100);
    cudaFuncSetAttribute(leaf_tc,     cudaFuncAttributePreferredSharedMemoryCarveout, 100);

    build_wt_int<<<(1600 * 640 + 255) / 256, 256>>>(Wiouh, Wfh);
    build_wt_leaf<<<(960 * 320 + 255) / 256, 256>>>(Wfioux);
    convert_x<<<(NLEAVES * NB * 320 + 255) / 256, 256>>>(inputs);

    leaf_tc<<<dim3(10, NLEAVES), 256, LSMEM_H * 2>>>(b_fioux);

    int base = NLEAVES;
    for (int k = NLEAVES / 2; k >= 1; k >>= 1) {
        internal_tc<<<dim3(10, k), 256, ISMEM_H * 2>>>(left_idx, right_idx, b_fioux, base);
        base += k;
    }
    copy_out<<<(2 * NB * MEM + 255) / 256, 256>>>(out);
}